// round 16
// baseline (speedup 1.0000x reference)
#include <cuda_runtime.h>
#include <cuda_bf16.h>
#include <math.h>
#include <stdint.h>

// Problem constants
#define B_  4
#define T_  512
#define J_  17
#define C_  256
#define H_  8
#define D_  32
#define NROWS 34816   // B_*T_*J_
#define NHEAD 544     // B_*J_*H_

// ---------------- scratch (static device allocations) ----------------
__device__ float g_y   [(size_t)NROWS * 512];
__device__ float g_kv  [(size_t)NROWS * 512];
__device__ float g_q   [(size_t)NROWS * 256];
__device__ float g_wc2t[512 * 256];
__device__ float g_wf  [256 * 512];
__device__ float g_bq  [256];

__device__ __align__(128) __nv_bfloat16 g_xh [(size_t)NROWS * 256];
__device__ __align__(128) __nv_bfloat16 g_xl [(size_t)NROWS * 256];
__device__ __align__(128) __nv_bfloat16 g_gh [(size_t)NROWS * 512];
__device__ __align__(128) __nv_bfloat16 g_gl [(size_t)NROWS * 512];
__device__ __align__(128) __nv_bfloat16 g_ath[(size_t)NROWS * 256];
__device__ __align__(128) __nv_bfloat16 g_atl[(size_t)NROWS * 256];
__device__ __align__(128) __nv_bfloat16 g_kh [(size_t)NHEAD * T_ * D_];
__device__ __align__(128) __nv_bfloat16 g_vth[(size_t)NHEAD * D_ * T_];
__device__ __align__(128) __nv_bfloat16 g_vtl[(size_t)NHEAD * D_ * T_];
__device__ __align__(128) __nv_bfloat16 g_wc1h[512 * 256];
__device__ __align__(128) __nv_bfloat16 g_wc1l[512 * 256];
__device__ __align__(128) __nv_bfloat16 g_wkvh[512 * 256];
__device__ __align__(128) __nv_bfloat16 g_wkvl[512 * 256];
__device__ __align__(128) __nv_bfloat16 g_wfh[256 * 512];
__device__ __align__(128) __nv_bfloat16 g_wfl[256 * 512];
__device__ __align__(128) __nv_bfloat16 g_wph[256 * 256];
__device__ __align__(128) __nv_bfloat16 g_wpl[256 * 256];

__device__ __forceinline__ float gelu_exact(float x) {
    return 0.5f * x * (1.0f + erff(x * 0.70710678118654752f));
}
__device__ __forceinline__ uint32_t pack_bf2(float a, float b) {
    __nv_bfloat162 t = __floats2bfloat162_rn(a, b);
    return *reinterpret_cast<uint32_t*>(&t);
}
__device__ __forceinline__ float bf16rt(float x) {
    return __bfloat162float(__float2bfloat16_rn(x));
}
__device__ __forceinline__ uint32_t smem_u32(const void* p) {
    uint32_t a;
    asm("{ .reg .u64 t; cvta.to.shared.u64 t, %1; cvt.u32.u64 %0, t; }" : "=r"(a) : "l"(p));
    return a;
}
__device__ __forceinline__ void mma16816(float* c, const uint32_t* a, const uint32_t* b) {
    asm volatile(
        "mma.sync.aligned.m16n8k16.row.col.f32.bf16.bf16.f32 "
        "{%0,%1,%2,%3}, {%4,%5,%6,%7}, {%8,%9}, {%0,%1,%2,%3};"
        : "+f"(c[0]), "+f"(c[1]), "+f"(c[2]), "+f"(c[3])
        : "r"(a[0]), "r"(a[1]), "r"(a[2]), "r"(a[3]), "r"(b[0]), "r"(b[1]));
}
#define LDSM4(R0, R1, R2, R3, ADDR) \
    asm volatile("ldmatrix.sync.aligned.m8n8.x4.shared.b16 {%0,%1,%2,%3}, [%4];" \
                 : "=r"(R0), "=r"(R1), "=r"(R2), "=r"(R3) : "r"(ADDR))

// Fast exp2 (FMA/ALU pipes only, no MUFU).
__device__ __forceinline__ float exp2n(float t) {
    t = fmaxf(t, -120.f);
    int k = __float2int_rn(t);
    float f = t - (float)k;
    float p = 1.3333558146428443e-3f;
    p = fmaf(p, f, 9.6181291076284771e-3f);
    p = fmaf(p, f, 5.5504108664821580e-2f);
    p = fmaf(p, f, 2.4022650695910072e-1f);
    p = fmaf(p, f, 6.9314718055994531e-1f);
    p = fmaf(p, f, 1.0f);
    return p * __int_as_float((k + 127) << 23);
}

// ---------------------------------------------------------------------------
// Prologue kernels
// ---------------------------------------------------------------------------
__global__ void transpose_wc2(const float* __restrict__ Wc2, float* __restrict__ Wc2T) {
    __shared__ float tile[32][33];
    const int bx = blockIdx.x, by = blockIdx.y;
    const int x = threadIdx.x, y = threadIdx.y;
#pragma unroll
    for (int i = 0; i < 32; i += 8)
        tile[y + i][x] = Wc2[(size_t)(by * 32 + y + i) * 512 + bx * 32 + x];
    __syncthreads();
#pragma unroll
    for (int i = 0; i < 32; i += 8)
        Wc2T[(size_t)(bx * 32 + y + i) * 256 + by * 32 + x] = tile[x][y + i];
}

__global__ void fold_bias(const float* __restrict__ Wq, const float* __restrict__ bc2,
                          float* __restrict__ bq) {
    const int o    = blockIdx.x * 8 + (threadIdx.x >> 5);
    const int lane = threadIdx.x & 31;
    float s = 0.f;
    for (int c = lane; c < 256; c += 32) s += Wq[o * 256 + c] * bc2[c];
#pragma unroll
    for (int off = 16; off; off >>= 1) s += __shfl_xor_sync(0xffffffffu, s, off);
    if (lane == 0) bq[o] = s;
}

__device__ __forceinline__ void split_one(const float4* src, uint2* dhi, uint2* dlo, int i) {
    const float4 v = src[i];
    const float hx = bf16rt(v.x), hy = bf16rt(v.y), hz = bf16rt(v.z), hw = bf16rt(v.w);
    dhi[i] = make_uint2(pack_bf2(hx, hy), pack_bf2(hz, hw));
    dlo[i] = make_uint2(pack_bf2(v.x - hx, v.y - hy), pack_bf2(v.z - hz, v.w - hw));
}

// Merged split for all weights + x (segment dispatch). Grid 9152 x 256.
__global__ void split_all(const float* __restrict__ Wc1, const float* __restrict__ Wkv,
                          const float* __restrict__ wf,  const float* __restrict__ Wp,
                          const float* __restrict__ x,
                          uint2* __restrict__ wc1h, uint2* __restrict__ wc1l,
                          uint2* __restrict__ wkvh, uint2* __restrict__ wkvl,
                          uint2* __restrict__ wfh,  uint2* __restrict__ wfl,
                          uint2* __restrict__ wph,  uint2* __restrict__ wpl,
                          uint2* __restrict__ xh,   uint2* __restrict__ xl) {
    const int i = blockIdx.x * 256 + threadIdx.x;
    if (i < 32768) {
        split_one((const float4*)Wc1, wc1h, wc1l, i);
    } else if (i < 65536) {
        split_one((const float4*)Wkv, wkvh, wkvl, i - 32768);
    } else if (i < 98304) {
        split_one((const float4*)wf, wfh, wfl, i - 65536);
    } else if (i < 114688) {
        split_one((const float4*)Wp, wph, wpl, i - 98304);
    } else {
        split_one((const float4*)x, xh, xl, i - 114688);   // NROWS*64 elems
    }
}

// ---------------------------------------------------------------------------
// conv_g body: one block handles 8*256 float4 positions of g.
// ---------------------------------------------------------------------------
__device__ __forceinline__ void conv_g_blk(const float* __restrict__ y,
                                           uint2* __restrict__ gh, uint2* __restrict__ gl,
                                           int blk) {
#pragma unroll
    for (int k = 0; k < 8; k++) {
        const int i = blk * 2048 + k * 256 + threadIdx.x;
        const int row = i >> 7;
        const int c4  = i & 127;
        const int t = (row / J_) % T_;
        float4 g;
        if (t == 0) {
            g = make_float4(0.f, 0.f, 0.f, 0.f);
        } else {
            const float* pc = y + (size_t)row * 512 + c4 * 4;
            float4 cu = *(const float4*)pc;
            float4 pv = *(const float4*)(pc - (size_t)J_ * 512);
            g.x = gelu_exact(cu.x - pv.x);
            g.y = gelu_exact(cu.y - pv.y);
            g.z = gelu_exact(cu.z - pv.z);
            g.w = gelu_exact(cu.w - pv.w);
        }
        const float hx = bf16rt(g.x), hy = bf16rt(g.y), hz = bf16rt(g.z), hw = bf16rt(g.w);
        gh[i] = make_uint2(pack_bf2(hx, hy), pack_bf2(hz, hw));
        gl[i] = make_uint2(pack_bf2(g.x - hx, g.y - hy), pack_bf2(g.z - hz, g.w - hw));
    }
}

// ---------------------------------------------------------------------------
// conv_kv body: idx in [0, 8704) -> head = idx>>4, t-chunk = idx&15.
// ---------------------------------------------------------------------------
__device__ __forceinline__ void conv_kv_blk(const float* __restrict__ kv,
                                            __nv_bfloat16* __restrict__ kh,
                                            __nv_bfloat16* __restrict__ vth,
                                            __nv_bfloat16* __restrict__ vtl, int idx) {
    __shared__ float sv[32][33];
    const int head = idx >> 4;
    const int t0   = (idx & 15) * 32;
    const int b    = head / (J_ * H_);
    const int rem  = head % (J_ * H_);
    const int j    = rem / H_;
    const int h    = rem % H_;
    const int d  = threadIdx.x & 31;
    const int tt = threadIdx.x >> 5;
#pragma unroll
    for (int i = 0; i < 4; i++) {
        const int t = t0 + tt + i * 8;
        const size_t row = ((size_t)(b * T_ + t) * J_ + j);
        const float kvv = kv[row * 512 + h * 32 + d];
        const size_t ko = ((size_t)head * T_ + t) * 32 + d;
        kh[ko] = __float2bfloat16_rn(kvv);
        sv[tt + i * 8][d] = kv[row * 512 + 256 + h * 32 + d];
    }
    __syncthreads();
#pragma unroll
    for (int i = 0; i < 4; i++) {
        const int dd = tt + i * 8;
        const float v = sv[d][dd];
        const float vhi = bf16rt(v);
        const size_t vo = ((size_t)head * 32 + dd) * T_ + t0 + d;
        vth[vo] = __float2bfloat16_rn(vhi);
        vtl[vo] = __float2bfloat16_rn(v - vhi);
    }
}

// ---------------------------------------------------------------------------
// fp32-input GEMM (prologue only, unchanged)
// ---------------------------------------------------------------------------
#define SPAD 40

__global__ __launch_bounds__(256, 2)
void gemm_f32(const float* __restrict__ A, const float* __restrict__ W,
              float* __restrict__ Cout, int K, int N)
{
    __shared__ __nv_bfloat16 Ahi[128][SPAD];
    __shared__ __nv_bfloat16 Alo[128][SPAD];
    __shared__ __nv_bfloat16 Bhi[64][SPAD];
    __shared__ __nv_bfloat16 Blo[64][SPAD];

    const int tid  = threadIdx.x;
    const int wid  = tid >> 5;
    const int lane = tid & 31;
    const int g    = lane >> 2;
    const int t2   = (lane & 3) << 1;
    const int warp_m = wid & 3;
    const int warp_n = wid >> 2;
    const int rowBase = blockIdx.y * 128;
    const int colBase = blockIdx.x * 64;

    const int a_row = warp_m * 32 + (lane & 15);
    const int a_col = (lane >> 4) * 8;
    const uint32_t aAhi0 = smem_u32(&Ahi[a_row][a_col]);
    const uint32_t aAhi1 = smem_u32(&Ahi[a_row + 16][a_col]);
    const uint32_t aAlo0 = smem_u32(&Alo[a_row][a_col]);
    const uint32_t aAlo1 = smem_u32(&Alo[a_row + 16][a_col]);
    const int b_row = warp_n * 32 + (lane & 7) + ((lane >> 4) << 3);
    const int b_col = ((lane >> 3) & 1) * 8;
    const uint32_t aBhi0 = smem_u32(&Bhi[b_row][b_col]);
    const uint32_t aBhi1 = smem_u32(&Bhi[b_row + 16][b_col]);
    const uint32_t aBlo0 = smem_u32(&Blo[b_row][b_col]);
    const uint32_t aBlo1 = smem_u32(&Blo[b_row + 16][b_col]);

    float acc[2][4][4];
#pragma unroll
    for (int mi = 0; mi < 2; mi++)
#pragma unroll
        for (int ni = 0; ni < 4; ni++)
#pragma unroll
            for (int e = 0; e < 4; e++) acc[mi][ni][e] = 0.f;

    const int nchunks = K >> 5;
    for (int ch = 0; ch < nchunks; ch++) {
        const int k0 = ch << 5;
#pragma unroll
        for (int i = 0; i < 4; i++) {
            const int idx = tid + i * 256;
            const int row = idx >> 3, c4 = idx & 7;
            const float4 v = *(const float4*)(A + (size_t)(rowBase + row) * K + k0 + c4 * 4);
            float hx = bf16rt(v.x), hy = bf16rt(v.y), hz = bf16rt(v.z), hw = bf16rt(v.w);
            *(uint2*)&Ahi[row][c4 * 4] = make_uint2(pack_bf2(hx, hy), pack_bf2(hz, hw));
            *(uint2*)&Alo[row][c4 * 4] = make_uint2(pack_bf2(v.x - hx, v.y - hy),
                                                    pack_bf2(v.z - hz, v.w - hw));
        }
#pragma unroll
        for (int i = 0; i < 2; i++) {
            const int idx = tid + i * 256;
            const int row = idx >> 3, c4 = idx & 7;
            const float4 v = *(const float4*)(W + (size_t)(colBase + row) * K + k0 + c4 * 4);
            float hx = bf16rt(v.x), hy = bf16rt(v.y), hz = bf16rt(v.z), hw = bf16rt(v.w);
            *(uint2*)&Bhi[row][c4 * 4] = make_uint2(pack_bf2(hx, hy), pack_bf2(hz, hw));
            *(uint2*)&Blo[row][c4 * 4] = make_uint2(pack_bf2(v.x - hx, v.y - hy),
                                                    pack_bf2(v.z - hz, v.w - hw));
        }
        __syncthreads();
#pragma unroll
        for (int ks = 0; ks < 2; ks++) {
            const uint32_t ko = ks * 32;
            uint32_t fAhi[2][4], fAlo[2][4], fBhi[4][2], fBlo[4][2];
            LDSM4(fAhi[0][0], fAhi[0][1], fAhi[0][2], fAhi[0][3], aAhi0 + ko);
            LDSM4(fAhi[1][0], fAhi[1][1], fAhi[1][2], fAhi[1][3], aAhi1 + ko);
            LDSM4(fAlo[0][0], fAlo[0][1], fAlo[0][2], fAlo[0][3], aAlo0 + ko);
            LDSM4(fAlo[1][0], fAlo[1][1], fAlo[1][2], fAlo[1][3], aAlo1 + ko);
            LDSM4(fBhi[0][0], fBhi[0][1], fBhi[1][0], fBhi[1][1], aBhi0 + ko);
            LDSM4(fBhi[2][0], fBhi[2][1], fBhi[3][0], fBhi[3][1], aBhi1 + ko);
            LDSM4(fBlo[0][0], fBlo[0][1], fBlo[1][0], fBlo[1][1], aBlo0 + ko);
            LDSM4(fBlo[2][0], fBlo[2][1], fBlo[3][0], fBlo[3][1], aBlo1 + ko);
#pragma unroll
            for (int mi = 0; mi < 2; mi++)
#pragma unroll
                for (int ni = 0; ni < 4; ni++) mma16816(acc[mi][ni], fAhi[mi], fBhi[ni]);
#pragma unroll
            for (int mi = 0; mi < 2; mi++)
#pragma unroll
                for (int ni = 0; ni < 4; ni++) mma16816(acc[mi][ni], fAhi[mi], fBlo[ni]);
#pragma unroll
            for (int mi = 0; mi < 2; mi++)
#pragma unroll
                for (int ni = 0; ni < 4; ni++) mma16816(acc[mi][ni], fAlo[mi], fBhi[ni]);
        }
        __syncthreads();
    }
#pragma unroll
    for (int mi = 0; mi < 2; mi++) {
        const int row0 = rowBase + warp_m * 32 + mi * 16 + g;
#pragma unroll
        for (int ni = 0; ni < 4; ni++) {
            const int col = colBase + warp_n * 32 + ni * 8 + t2;
            *(float2*)(Cout + (size_t)row0 * N + col)       = make_float2(acc[mi][ni][0], acc[mi][ni][1]);
            *(float2*)(Cout + (size_t)(row0 + 8) * N + col) = make_float2(acc[mi][ni][2], acc[mi][ni][3]);
        }
    }
}

// ---------------------------------------------------------------------------
// bf16-input GEMM tile as device function (double-buffered, one barrier/chunk)
// ---------------------------------------------------------------------------
#define STAGE_BYTES 30720
#define A_LO_OFF    10240
#define B_HI_OFF    20480
#define B_LO_OFF    25600
#define GEMM_DYN_SMEM (2 * STAGE_BYTES)

__device__ __forceinline__ void gemm_bf_tile(
    const __nv_bfloat16* __restrict__ Ah, const __nv_bfloat16* __restrict__ Al,
    const __nv_bfloat16* __restrict__ Wh, const __nv_bfloat16* __restrict__ Wl,
    const float* __restrict__ bias, float* __restrict__ Cout,
    int K, int N, int rowBase, int colBase, uint8_t* dynsm)
{
    __shared__ float s_bias[64];
    const uint32_t sbase = smem_u32(dynsm);
    const int tid  = threadIdx.x;
    const int wid  = tid >> 5;
    const int lane = tid & 31;
    const int g    = lane >> 2;
    const int t2   = (lane & 3) << 1;
    const int warp_m = wid & 3;
    const int warp_n = wid >> 2;

    if (tid < 64) s_bias[tid] = bias ? bias[colBase + tid] : 0.f;

    const int a_row = warp_m * 32 + (lane & 15);
    const int a_col = (lane >> 4) * 8;
    const uint32_t oAhi0 = (uint32_t)(a_row * SPAD + a_col) * 2;
    const uint32_t oAhi1 = oAhi0 + 16 * SPAD * 2;
    const uint32_t oAlo0 = oAhi0 + A_LO_OFF;
    const uint32_t oAlo1 = oAhi1 + A_LO_OFF;
    const int b_row = warp_n * 32 + (lane & 7) + ((lane >> 4) << 3);
    const int b_col = ((lane >> 3) & 1) * 8;
    const uint32_t oBhi0 = B_HI_OFF + (uint32_t)(b_row * SPAD + b_col) * 2;
    const uint32_t oBhi1 = oBhi0 + 16 * SPAD * 2;
    const uint32_t oBlo0 = oBhi0 + (B_LO_OFF - B_HI_OFF);
    const uint32_t oBlo1 = oBhi1 + (B_LO_OFF - B_HI_OFF);

    const int ar0 = tid >> 2, as0 = (tid & 3) * 8;
    const uint32_t sA0 = (uint32_t)(ar0 * SPAD + as0) * 2;
    const uint32_t sA1 = (uint32_t)((ar0 + 64) * SPAD + as0) * 2;
    const uint32_t sB  = B_HI_OFF + (uint32_t)(ar0 * SPAD + as0) * 2;

    float acc[2][4][4];
#pragma unroll
    for (int mi = 0; mi < 2; mi++)
#pragma unroll
        for (int ni = 0; ni < 4; ni++)
#pragma unroll
            for (int e = 0; e < 4; e++) acc[mi][ni][e] = 0.f;

    const int nchunks = K >> 5;
    uint4 pah[2], pal[2], pbh, pbl;

    auto prefetch = [&](int ch) {
        const int k0 = ch << 5;
#pragma unroll
        for (int i = 0; i < 2; i++) {
            const int row = ar0 + i * 64;
            pah[i] = *(const uint4*)(Ah + (size_t)(rowBase + row) * K + k0 + as0);
            pal[i] = *(const uint4*)(Al + (size_t)(rowBase + row) * K + k0 + as0);
        }
        pbh = *(const uint4*)(Wh + (size_t)(colBase + ar0) * K + k0 + as0);
        pbl = *(const uint4*)(Wl + (size_t)(colBase + ar0) * K + k0 + as0);
    };

    prefetch(0);

    for (int ch = 0; ch < nchunks; ch++) {
        const uint32_t soff = (uint32_t)(ch & 1) * STAGE_BYTES;
        uint8_t* stg = dynsm + soff;
        *(uint4*)(stg + sA0)            = pah[0];
        *(uint4*)(stg + sA1)            = pah[1];
        *(uint4*)(stg + sA0 + A_LO_OFF) = pal[0];
        *(uint4*)(stg + sA1 + A_LO_OFF) = pal[1];
        *(uint4*)(stg + sB)             = pbh;
        *(uint4*)(stg + sB + (B_LO_OFF - B_HI_OFF)) = pbl;
        __syncthreads();

        if (ch + 1 < nchunks) prefetch(ch + 1);

        const uint32_t sb = sbase + soff;
#pragma unroll
        for (int ks = 0; ks < 2; ks++) {
            const uint32_t ko = ks * 32;
            uint32_t fAhi[2][4], fAlo[2][4], fBhi[4][2], fBlo[4][2];
            LDSM4(fAhi[0][0], fAhi[0][1], fAhi[0][2], fAhi[0][3], sb + oAhi0 + ko);
            LDSM4(fAhi[1][0], fAhi[1][1], fAhi[1][2], fAhi[1][3], sb + oAhi1 + ko);
            LDSM4(fAlo[0][0], fAlo[0][1], fAlo[0][2], fAlo[0][3], sb + oAlo0 + ko);
            LDSM4(fAlo[1][0], fAlo[1][1], fAlo[1][2], fAlo[1][3], sb + oAlo1 + ko);
            LDSM4(fBhi[0][0], fBhi[0][1], fBhi[1][0], fBhi[1][1], sb + oBhi0 + ko);
            LDSM4(fBhi[2][0], fBhi[2][1], fBhi[3][0], fBhi[3][1], sb + oBhi1 + ko);
            LDSM4(fBlo[0][0], fBlo[0][1], fBlo[1][0], fBlo[1][1], sb + oBlo0 + ko);
            LDSM4(fBlo[2][0], fBlo[2][1], fBlo[3][0], fBlo[3][1], sb + oBlo1 + ko);
#pragma unroll
            for (int mi = 0; mi < 2; mi++)
#pragma unroll
                for (int ni = 0; ni < 4; ni++) mma16816(acc[mi][ni], fAhi[mi], fBhi[ni]);
#pragma unroll
            for (int mi = 0; mi < 2; mi++)
#pragma unroll
                for (int ni = 0; ni < 4; ni++) mma16816(acc[mi][ni], fAhi[mi], fBlo[ni]);
#pragma unroll
            for (int mi = 0; mi < 2; mi++)
#pragma unroll
                for (int ni = 0; ni < 4; ni++) mma16816(acc[mi][ni], fAlo[mi], fBhi[ni]);
        }
    }

#pragma unroll
    for (int mi = 0; mi < 2; mi++) {
        const int row0 = rowBase + warp_m * 32 + mi * 16 + g;
#pragma unroll
        for (int ni = 0; ni < 4; ni++) {
            const int cl = warp_n * 32 + ni * 8 + t2;
            const int col = colBase + cl;
            const float bx = s_bias[cl], by = s_bias[cl + 1];
            *(float2*)(Cout + (size_t)row0 * N + col) =
                make_float2(acc[mi][ni][0] + bx, acc[mi][ni][1] + by);
            *(float2*)(Cout + (size_t)(row0 + 8) * N + col) =
                make_float2(acc[mi][ni][2] + bx, acc[mi][ni][3] + by);
        }
    }
}

// Standalone GEMM kernel (for y and out)
__global__ __launch_bounds__(256, 2)
void gemm_bf(const __nv_bfloat16* __restrict__ Ah, const __nv_bfloat16* __restrict__ Al,
             const __nv_bfloat16* __restrict__ Wh, const __nv_bfloat16* __restrict__ Wl,
             const float* __restrict__ bias, float* __restrict__ Cout, int K, int N)
{
    extern __shared__ __align__(128) uint8_t dynsm[];
    gemm_bf_tile(Ah, Al, Wh, Wl, bias, Cout, K, N,
                 blockIdx.y * 128, blockIdx.x * 64, dynsm);
}

// Fused: even blocks = gemm_kv tile, odd blocks = conv_g (8x work).
// conv_g depends on y (previous launch); gemm_kv independent -> overlap.
__global__ __launch_bounds__(256, 2)
void fused_kv_g(const __nv_bfloat16* __restrict__ xh, const __nv_bfloat16* __restrict__ xl,
                const __nv_bfloat16* __restrict__ wkvh, const __nv_bfloat16* __restrict__ wkvl,
                float* __restrict__ kv,
                const float* __restrict__ y,
                uint2* __restrict__ gh, uint2* __restrict__ gl)
{
    extern __shared__ __align__(128) uint8_t dynsm[];
    const int bx = blockIdx.x;   // 0..4351
    if ((bx & 1) == 0) {
        const int t = bx >> 1;   // 0..2175
        gemm_bf_tile(xh, xl, wkvh, wkvl, nullptr, kv, 256, 512,
                     (t >> 3) * 128, (t & 7) * 64, dynsm);
    } else {
        conv_g_blk(y, gh, gl, bx >> 1);
    }
}

// Fused: every 9th block = gemm_q tile, rest = conv_kv.
// conv_kv depends on kv (previous launch); gemm_q depends on g (prev-prev).
__global__ __launch_bounds__(256, 2)
void fused_q_ckv(const __nv_bfloat16* __restrict__ gh, const __nv_bfloat16* __restrict__ gl,
                 const __nv_bfloat16* __restrict__ wfh, const __nv_bfloat16* __restrict__ wfl,
                 const float* __restrict__ bq, float* __restrict__ q,
                 const float* __restrict__ kv,
                 __nv_bfloat16* __restrict__ kh,
                 __nv_bfloat16* __restrict__ vth, __nv_bfloat16* __restrict__ vtl)
{
    extern __shared__ __align__(128) uint8_t dynsm[];
    const int bx = blockIdx.x;   // 0..9791
    const int grp = bx / 9, r = bx % 9;
    if (r == 0) {
        const int t = grp;       // 0..1087
        gemm_bf_tile(gh, gl, wfh, wfl, bq, q, 512, 256,
                     (t >> 2) * 128, (t & 3) * 64, dynsm);
    } else {
        conv_kv_blk(kv, kh, vth, vtl, grp * 8 + r - 1);   // 0..8703
    }
}

// ---------------------------------------------------------------------------
// Tensor-core flash attention (unchanged from R15)
// ---------------------------------------------------------------------------
#define ACHUNK 128
#define VSPAD  136
#define AST_VHI 10240
#define AST_VLO 18944
#define AST_BYTES 27648
#define ATTN_DYN_SMEM (2 * AST_BYTES)

__global__ __launch_bounds__(256)
void attn_mma(const float* __restrict__ q,
              const __nv_bfloat16* __restrict__ khg,
              const __nv_bfloat16* __restrict__ vthg, const __nv_bfloat16* __restrict__ vtlg,
              __nv_bfloat16* __restrict__ ath, __nv_bfloat16* __restrict__ atl)
{
    extern __shared__ __align__(128) uint8_t dynsm[];

    const int bx    = blockIdx.x;
    const int head  = bx >> 1;
    const int qhalf = bx & 1;
    const int b   = head / (J_ * H_);
    const int rem = head % (J_ * H_);
    const int j   = rem / H_;
    const int h   = rem % H_;
    const int tid  = threadIdx.x;
    const int wid  = tid >> 5;
    const int lane = tid & 31;
    const int g    = lane >> 2;
    const int t2   = (lane & 3) << 1;

    const uint32_t sbase = smem_u32(dynsm);

    const __nv_bfloat16* khb = khg + (size_t)head * T_ * D_;
    const __nv_bfloat16* vhb = vthg + (size_t)head * D_ * T_;
    const __nv_bfloat16* vlb = vtlg + (size_t)head * D_ * T_;

    const size_t qStride = (size_t)J_ * C_;
    const float* qb = q + (size_t)b * T_ * J_ * C_ + (size_t)j * C_ + h * D_;
    const size_t atoff = (size_t)b * T_ * J_ * C_ + (size_t)j * C_ + h * D_;

    const int qbase = qhalf * 256 + wid * 32;

    const int k_row = (lane & 7) + ((lane >> 4) << 3);
    const int k_col = ((lane >> 3) & 1) * 8;
    const uint32_t oKhi = (uint32_t)(k_row * SPAD + k_col) * 2;
    const uint32_t oVhi0 = AST_VHI + (uint32_t)(k_row * VSPAD + k_col) * 2;
    const uint32_t oVhi1 = oVhi0 + 16 * VSPAD * 2;
    const uint32_t oVlo0 = oVhi0 + (AST_VLO - AST_VHI);
    const uint32_t oVlo1 = oVhi1 + (AST_VLO - AST_VHI);

    const float qscale = 0.17677669529663687f * 1.4426950408889634f;
    uint32_t Qhi[2][2][4];
#pragma unroll
    for (int mt = 0; mt < 2; mt++)
#pragma unroll
        for (int kt = 0; kt < 2; kt++)
#pragma unroll
            for (int e = 0; e < 4; e++) {
                const int row = qbase + mt * 16 + g + ((e & 1) ? 8 : 0);
                const int col = kt * 16 + t2 + ((e & 2) ? 8 : 0);
                float2 v = *(const float2*)(qb + (size_t)row * qStride + col);
                Qhi[mt][kt][e] = pack_bf2(v.x * qscale, v.y * qscale);
            }

    float O[2][4][4];
#pragma unroll
    for (int mt = 0; mt < 2; mt++)
#pragma unroll
        for (int d = 0; d < 4; d++)
#pragma unroll
            for (int e = 0; e < 4; e++) O[mt][d][e] = 0.f;
    float l[2][2] = {{0.f, 0.f}, {0.f, 0.f}};

    const int nchunks = T_ / ACHUNK;   // 4
    for (int cc = 0; cc < nchunks; cc++) {
        const int c0 = cc * ACHUNK;
        const uint32_t soff = (uint32_t)(cc & 1) * AST_BYTES;
        uint8_t* stg = dynsm + soff;

        for (int i = tid; i < 512; i += 256) {
            const int r = i >> 2, seg = (i & 3) * 8;
            *(uint4*)(stg + (uint32_t)(r * SPAD + seg) * 2) =
                *(const uint4*)(khb + (size_t)(c0 + r) * D_ + seg);
        }
        for (int i = tid; i < 512; i += 256) {
            const int d = i >> 4, seg = (i & 15) * 8;
            *(uint4*)(stg + AST_VHI + (uint32_t)(d * VSPAD + seg) * 2) =
                *(const uint4*)(vhb + (size_t)d * T_ + c0 + seg);
            *(uint4*)(stg + AST_VLO + (uint32_t)(d * VSPAD + seg) * 2) =
                *(const uint4*)(vlb + (size_t)d * T_ + c0 + seg);
        }
        __syncthreads();

        const uint32_t sb = sbase + soff;
#pragma unroll 1
        for (int s = 0; s < ACHUNK / 16; s++) {
            const int key0 = s * 16;
            const uint32_t krow_off = (uint32_t)key0 * (SPAD * 2);
            const uint32_t vcol_off = (uint32_t)key0 * 2;

            uint32_t kh[2][2][2];
            LDSM4(kh[0][0][0], kh[0][0][1], kh[1][0][0], kh[1][0][1], sb + oKhi + krow_off);
            LDSM4(kh[0][1][0], kh[0][1][1], kh[1][1][0], kh[1][1][1], sb + oKhi + krow_off + 32);

            float S[2][2][4];
#pragma unroll
            for (int mt = 0; mt < 2; mt++)
#pragma unroll
                for (int nt = 0; nt < 2; nt++)
#pragma unroll
                    for (int e = 0; e < 4; e++) S[mt][nt][e] = 0.f;
#pragma unroll
            for (int mt = 0; mt < 2; mt++)
#pragma unroll
                for (int nt = 0; nt < 2; nt++) mma16816(S[mt][nt], Qhi[mt][0], kh[nt][0]);
#pragma unroll
            for (int mt = 0; mt < 2; mt++)
#pragma unroll
                for (int nt = 0; nt < 2; nt++) mma16816(S[mt][nt], Qhi[mt][1], kh[nt][1]);

            uint32_t vh[4][2], vl[4][2];
            LDSM4(vh[0][0], vh[0][1], vh[1][0], vh[1][1], sb + oVhi0 + vcol_off);
            LDSM4(vh[2][0], vh[2][1], vh[3][0], vh[3][1], sb + oVhi1 + vcol_off);
            LDSM4(vl[0][0], vl[0][1], vl[1][0], vl[1][1], sb + oVlo0 + vcol_off);
            LDSM4(vl[2][0], vl[2][1], vl[3][0], vl[3][1], sb + oVlo1 + vcol_off);

            uint32_t Ph[2][4], Pl[2][4];
#pragma unroll
            for (int mt = 0; mt < 2; mt++) {
                const float p00 = exp2n(S[mt][0][0]);
                const float p01 = exp2n(S[mt][0][1]);
                const float p02 = exp2n(S[mt][0][2]);
                const float p03 = exp2n(S[mt][0][3]);
                const float p10 = exp2n(S[mt][1][0]);
                const float p11 = exp2n(S[mt][1][1]);
                const float p12 = exp2n(S[mt][1][2]);
                const float p13 = exp2n(S[mt][1][3]);
                l[mt][0] += p00 + p01 + p10 + p11;
                l[mt][1] += p02 + p03 + p12 + p13;
                float h00 = bf16rt(p00), h01 = bf16rt(p01), h02 = bf16rt(p02), h03 = bf16rt(p03);
                float h10 = bf16rt(p10), h11 = bf16rt(p11), h12 = bf16rt(p12), h13 = bf16rt(p13);
                Ph[mt][0] = pack_bf2(h00, h01); Pl[mt][0] = pack_bf2(p00 - h00, p01 - h01);
                Ph[mt][1] = pack_bf2(h02, h03); Pl[mt][1] = pack_bf2(p02 - h02, p03 - h03);
                Ph[mt][2] = pack_bf2(h10, h11); Pl[mt][2] = pack_bf2(p10 - h10, p11 - h11);
                Ph[mt][3] = pack_bf2(h12, h13); Pl[mt][3] = pack_bf2(p12 - h12, p13 - h13);
            }

#pragma unroll
            for (int mt = 0; mt < 2; mt++)
#pragma unroll
                for (int dn = 0; dn < 4; dn++) mma16816(O[mt][dn], Ph[mt], vh[dn]);
#pragma unroll
            for (int mt = 0; mt < 2; mt++)
#pragma unroll
                for (int dn = 0; dn < 4; dn++) mma16816(O[mt][dn], Ph[mt], vl[dn]);
#pragma unroll
            for (int mt = 0; mt < 2; mt++)
#pragma unroll
                for (int dn = 0; dn < 4; dn++) mma16816(O[mt][dn], Pl[mt], vh[dn]);
        }
    }

#pragma unroll
    for (int mt = 0; mt < 2; mt++) {
        float l0 = l[mt][0], l1 = l[mt][1];
        l0 += __shfl_xor_sync(0xffffffffu, l0, 1);
        l0 += __shfl_xor_sync(0xffffffffu, l0, 2);
        l1 += __shfl_xor_sync(0xffffffffu, l1, 1);
        l1 += __shfl_xor_sync(0xffffffffu, l1, 2);
        const float inv0 = 1.f / l0;
        const float inv1 = 1.f / l1;
        const int r0 = qbase + mt * 16 + g;
        const int r1 = r0 + 8;
#pragma unroll
        for (int dn = 0; dn < 4; dn++) {
            const int col = dn * 8 + t2;
            const float a0 = O[mt][dn][0] * inv0, a1 = O[mt][dn][1] * inv0;
            const float a2 = O[mt][dn][2] * inv1, a3 = O[mt][dn][3] * inv1;
            const float h0 = bf16rt(a0), h1 = bf16rt(a1), h2 = bf16rt(a2), h3 = bf16rt(a3);
            *(uint32_t*)(ath + atoff + (size_t)r0 * qStride + col) = pack_bf2(h0, h1);
            *(uint32_t*)(atl + atoff + (size_t)r0 * qStride + col) = pack_bf2(a0 - h0, a1 - h1);
            *(uint32_t*)(ath + atoff + (size_t)r1 * qStride + col) = pack_bf2(h2, h3);
            *(uint32_t*)(atl + atoff + (size_t)r1 * qStride + col) = pack_bf2(a2 - h2, a3 - h3);
        }
    }
}

// ---------------------------------------------------------------------------
extern "C" void kernel_launch(void* const* d_in, const int* in_sizes, int n_in,
                              void* d_out, int out_size)
{
    (void)in_sizes; (void)n_in; (void)out_size;
    const float* x   = (const float*)d_in[0];
    const float* Wq  = (const float*)d_in[1];
    const float* Wkv = (const float*)d_in[2];
    const float* Wc1 = (const float*)d_in[3];
    const float* bc1 = (const float*)d_in[4];
    const float* Wc2 = (const float*)d_in[5];
    const float* bc2 = (const float*)d_in[6];
    const float* Wp  = (const float*)d_in[7];
    const float* bp  = (const float*)d_in[8];
    float* out = (float*)d_out;

    float *y, *kv, *q, *wc2t, *wf, *bq;
    cudaGetSymbolAddress((void**)&y,    g_y);
    cudaGetSymbolAddress((void**)&kv,   g_kv);
    cudaGetSymbolAddress((void**)&q,    g_q);
    cudaGetSymbolAddress((void**)&wc2t, g_wc2t);
    cudaGetSymbolAddress((void**)&wf,   g_wf);
    cudaGetSymbolAddress((void**)&bq,   g_bq);

    __nv_bfloat16 *xh, *xl, *gh, *gl, *ath, *atl, *kh, *vth, *vtl;
    __nv_bfloat16 *wc1h, *wc1l, *wkvh, *wkvl, *wfh, *wfl, *wph, *wpl;
    cudaGetSymbolAddress((void**)&xh,  g_xh);   cudaGetSymbolAddress((void**)&xl,  g_xl);
    cudaGetSymbolAddress((void**)&gh,  g_gh);   cudaGetSymbolAddress((void**)&gl,  g_gl);
    cudaGetSymbolAddress((void**)&ath, g_ath);  cudaGetSymbolAddress((void**)&atl, g_atl);
    cudaGetSymbolAddress((void**)&kh,  g_kh);
    cudaGetSymbolAddress((void**)&vth, g_vth);  cudaGetSymbolAddress((void**)&vtl, g_vtl);
    cudaGetSymbolAddress((void**)&wc1h, g_wc1h); cudaGetSymbolAddress((void**)&wc1l, g_wc1l);
    cudaGetSymbolAddress((void**)&wkvh, g_wkvh); cudaGetSymbolAddress((void**)&wkvl, g_wkvl);
    cudaGetSymbolAddress((void**)&wfh,  g_wfh);  cudaGetSymbolAddress((void**)&wfl,  g_wfl);
    cudaGetSymbolAddress((void**)&wph,  g_wph);  cudaGetSymbolAddress((void**)&wpl,  g_wpl);

    cudaFuncSetAttribute(gemm_bf,    cudaFuncAttributeMaxDynamicSharedMemorySize, GEMM_DYN_SMEM);
    cudaFuncSetAttribute(fused_kv_g, cudaFuncAttributeMaxDynamicSharedMemorySize, GEMM_DYN_SMEM);
    cudaFuncSetAttribute(fused_q_ckv,cudaFuncAttributeMaxDynamicSharedMemorySize, GEMM_DYN_SMEM);
    cudaFuncSetAttribute(attn_mma,   cudaFuncAttributeMaxDynamicSharedMemorySize, ATTN_DYN_SMEM);

    const dim3 blk(256);
    const int mt = NROWS / 128;  // 272 row tiles

    // --- prologue: weight folding + merged splits ---
    transpose_wc2<<<dim3(16, 8), dim3(32, 8)>>>(Wc2, wc2t);
    gemm_f32<<<dim3(8, 2), blk>>>(Wq, wc2t, wf, 256, 512);
    fold_bias<<<32, 256>>>(Wq, bc2, bq);
    split_all<<<9152, 256>>>(Wc1, Wkv, wf, Wp, x,
                             (uint2*)wc1h, (uint2*)wc1l, (uint2*)wkvh, (uint2*)wkvl,
                             (uint2*)wfh, (uint2*)wfl, (uint2*)wph, (uint2*)wpl,
                             (uint2*)xh, (uint2*)xl);

    // --- main pipeline with block-striped overlap ---
    gemm_bf<<<dim3(8, mt), blk, GEMM_DYN_SMEM>>>(xh, xl, wc1h, wc1l, bc1, y, 256, 512);
    fused_kv_g<<<4352, blk, GEMM_DYN_SMEM>>>(xh, xl, wkvh, wkvl, kv, y, (uint2*)gh, (uint2*)gl);
    fused_q_ckv<<<9792, blk, GEMM_DYN_SMEM>>>(gh, gl, wfh, wfl, bq, q, kv, kh, vth, vtl);
    attn_mma<<<NHEAD * 2, 256, ATTN_DYN_SMEM>>>(q, kh, vth, vtl, ath, atl);
    gemm_bf<<<dim3(4, mt), blk, GEMM_DYN_SMEM>>>(ath, atl, wph, wpl, bp, out, 256, 256);
}

// round 17
// speedup vs baseline: 1.0421x; 1.0421x over previous
#include <cuda_runtime.h>
#include <cuda_bf16.h>
#include <math.h>
#include <stdint.h>

// Problem constants
#define B_  4
#define T_  512
#define J_  17
#define C_  256
#define H_  8
#define D_  32
#define NROWS 34816   // B_*T_*J_
#define NHEAD 544     // B_*J_*H_

// ---------------- scratch (static device allocations) ----------------
__device__ float g_y   [(size_t)NROWS * 512];
__device__ float g_kv  [(size_t)NROWS * 512];
__device__ float g_q   [(size_t)NROWS * 256];
__device__ float g_wc2t[512 * 256];
__device__ float g_wf  [256 * 512];
__device__ float g_bq  [256];

__device__ __align__(128) __nv_bfloat16 g_xh [(size_t)NROWS * 256];
__device__ __align__(128) __nv_bfloat16 g_xl [(size_t)NROWS * 256];
__device__ __align__(128) __nv_bfloat16 g_gh [(size_t)NROWS * 512];
__device__ __align__(128) __nv_bfloat16 g_gl [(size_t)NROWS * 512];
__device__ __align__(128) __nv_bfloat16 g_ath[(size_t)NROWS * 256];
__device__ __align__(128) __nv_bfloat16 g_atl[(size_t)NROWS * 256];
__device__ __align__(128) __nv_bfloat16 g_kh [(size_t)NHEAD * T_ * D_];
__device__ __align__(128) __nv_bfloat16 g_vth[(size_t)NHEAD * D_ * T_];
__device__ __align__(128) __nv_bfloat16 g_vtl[(size_t)NHEAD * D_ * T_];
__device__ __align__(128) __nv_bfloat16 g_wc1h[512 * 256];
__device__ __align__(128) __nv_bfloat16 g_wc1l[512 * 256];
__device__ __align__(128) __nv_bfloat16 g_wkvh[512 * 256];
__device__ __align__(128) __nv_bfloat16 g_wkvl[512 * 256];
__device__ __align__(128) __nv_bfloat16 g_wfh[256 * 512];
__device__ __align__(128) __nv_bfloat16 g_wfl[256 * 512];
__device__ __align__(128) __nv_bfloat16 g_wph[256 * 256];
__device__ __align__(128) __nv_bfloat16 g_wpl[256 * 256];

__device__ __forceinline__ float gelu_exact(float x) {
    return 0.5f * x * (1.0f + erff(x * 0.70710678118654752f));
}
__device__ __forceinline__ uint32_t pack_bf2(float a, float b) {
    __nv_bfloat162 t = __floats2bfloat162_rn(a, b);
    return *reinterpret_cast<uint32_t*>(&t);
}
__device__ __forceinline__ float bf16rt(float x) {
    return __bfloat162float(__float2bfloat16_rn(x));
}
__device__ __forceinline__ uint32_t smem_u32(const void* p) {
    uint32_t a;
    asm("{ .reg .u64 t; cvta.to.shared.u64 t, %1; cvt.u32.u64 %0, t; }" : "=r"(a) : "l"(p));
    return a;
}
__device__ __forceinline__ void mma16816(float* c, const uint32_t* a, const uint32_t* b) {
    asm volatile(
        "mma.sync.aligned.m16n8k16.row.col.f32.bf16.bf16.f32 "
        "{%0,%1,%2,%3}, {%4,%5,%6,%7}, {%8,%9}, {%0,%1,%2,%3};"
        : "+f"(c[0]), "+f"(c[1]), "+f"(c[2]), "+f"(c[3])
        : "r"(a[0]), "r"(a[1]), "r"(a[2]), "r"(a[3]), "r"(b[0]), "r"(b[1]));
}
#define LDSM4(R0, R1, R2, R3, ADDR) \
    asm volatile("ldmatrix.sync.aligned.m8n8.x4.shared.b16 {%0,%1,%2,%3}, [%4];" \
                 : "=r"(R0), "=r"(R1), "=r"(R2), "=r"(R3) : "r"(ADDR))

// Fast exp2 (FMA/ALU pipes only, no MUFU).
__device__ __forceinline__ float exp2n(float t) {
    t = fmaxf(t, -120.f);
    int k = __float2int_rn(t);
    float f = t - (float)k;
    float p = 1.3333558146428443e-3f;
    p = fmaf(p, f, 9.6181291076284771e-3f);
    p = fmaf(p, f, 5.5504108664821580e-2f);
    p = fmaf(p, f, 2.4022650695910072e-1f);
    p = fmaf(p, f, 6.9314718055994531e-1f);
    p = fmaf(p, f, 1.0f);
    return p * __int_as_float((k + 127) << 23);
}

// ---------------------------------------------------------------------------
// Prologue kernels
// ---------------------------------------------------------------------------
__global__ void transpose_wc2(const float* __restrict__ Wc2, float* __restrict__ Wc2T) {
    __shared__ float tile[32][33];
    const int bx = blockIdx.x, by = blockIdx.y;
    const int x = threadIdx.x, y = threadIdx.y;
#pragma unroll
    for (int i = 0; i < 32; i += 8)
        tile[y + i][x] = Wc2[(size_t)(by * 32 + y + i) * 512 + bx * 32 + x];
    __syncthreads();
#pragma unroll
    for (int i = 0; i < 32; i += 8)
        Wc2T[(size_t)(bx * 32 + y + i) * 256 + by * 32 + x] = tile[x][y + i];
}

__global__ void fold_bias(const float* __restrict__ Wq, const float* __restrict__ bc2,
                          float* __restrict__ bq) {
    const int o    = blockIdx.x * 8 + (threadIdx.x >> 5);
    const int lane = threadIdx.x & 31;
    float s = 0.f;
    for (int c = lane; c < 256; c += 32) s += Wq[o * 256 + c] * bc2[c];
#pragma unroll
    for (int off = 16; off; off >>= 1) s += __shfl_xor_sync(0xffffffffu, s, off);
    if (lane == 0) bq[o] = s;
}

__device__ __forceinline__ void split_one(const float4* src, uint2* dhi, uint2* dlo, int i) {
    const float4 v = src[i];
    const float hx = bf16rt(v.x), hy = bf16rt(v.y), hz = bf16rt(v.z), hw = bf16rt(v.w);
    dhi[i] = make_uint2(pack_bf2(hx, hy), pack_bf2(hz, hw));
    dlo[i] = make_uint2(pack_bf2(v.x - hx, v.y - hy), pack_bf2(v.z - hz, v.w - hw));
}

// Merged split for all weights + x (segment dispatch). Grid 9152 x 256.
__global__ void split_all(const float* __restrict__ Wc1, const float* __restrict__ Wkv,
                          const float* __restrict__ wf,  const float* __restrict__ Wp,
                          const float* __restrict__ x,
                          uint2* __restrict__ wc1h, uint2* __restrict__ wc1l,
                          uint2* __restrict__ wkvh, uint2* __restrict__ wkvl,
                          uint2* __restrict__ wfh,  uint2* __restrict__ wfl,
                          uint2* __restrict__ wph,  uint2* __restrict__ wpl,
                          uint2* __restrict__ xh,   uint2* __restrict__ xl) {
    const int i = blockIdx.x * 256 + threadIdx.x;
    if (i < 32768) {
        split_one((const float4*)Wc1, wc1h, wc1l, i);
    } else if (i < 65536) {
        split_one((const float4*)Wkv, wkvh, wkvl, i - 32768);
    } else if (i < 98304) {
        split_one((const float4*)wf, wfh, wfl, i - 65536);
    } else if (i < 114688) {
        split_one((const float4*)Wp, wph, wpl, i - 98304);
    } else {
        split_one((const float4*)x, xh, xl, i - 114688);   // NROWS*64 elems
    }
}

// ---------------------------------------------------------------------------
// conv_g: g = gelu(y[row] - y[row-J]) (t==0 -> 0), split hi/lo. (standalone)
// ---------------------------------------------------------------------------
__global__ void conv_g(const float* __restrict__ y,
                       uint2* __restrict__ gh, uint2* __restrict__ gl) {
    const int i = blockIdx.x * 256 + threadIdx.x;
    const int row = i >> 7;
    const int c4  = i & 127;
    const int t = (row / J_) % T_;
    float4 g;
    if (t == 0) {
        g = make_float4(0.f, 0.f, 0.f, 0.f);
    } else {
        const float* pc = y + (size_t)row * 512 + c4 * 4;
        float4 cu = *(const float4*)pc;
        float4 pv = *(const float4*)(pc - (size_t)J_ * 512);
        g.x = gelu_exact(cu.x - pv.x);
        g.y = gelu_exact(cu.y - pv.y);
        g.z = gelu_exact(cu.z - pv.z);
        g.w = gelu_exact(cu.w - pv.w);
    }
    const float hx = bf16rt(g.x), hy = bf16rt(g.y), hz = bf16rt(g.z), hw = bf16rt(g.w);
    gh[i] = make_uint2(pack_bf2(hx, hy), pack_bf2(hz, hw));
    gl[i] = make_uint2(pack_bf2(g.x - hx, g.y - hy), pack_bf2(g.z - hz, g.w - hw));
}

// ---------------------------------------------------------------------------
// conv_kv: kv -> per-head K[t][d] (hi only) and transposed Vt hi/lo. (standalone)
// ---------------------------------------------------------------------------
__global__ void conv_kv(const float* __restrict__ kv,
                        __nv_bfloat16* __restrict__ kh,
                        __nv_bfloat16* __restrict__ vth, __nv_bfloat16* __restrict__ vtl) {
    __shared__ float sv[32][33];
    const int head = blockIdx.y;
    const int t0   = blockIdx.x * 32;
    const int b    = head / (J_ * H_);
    const int rem  = head % (J_ * H_);
    const int j    = rem / H_;
    const int h    = rem % H_;
    const int d  = threadIdx.x & 31;
    const int tt = threadIdx.x >> 5;
#pragma unroll
    for (int i = 0; i < 4; i++) {
        const int t = t0 + tt + i * 8;
        const size_t row = ((size_t)(b * T_ + t) * J_ + j);
        const float kvv = kv[row * 512 + h * 32 + d];
        const size_t ko = ((size_t)head * T_ + t) * 32 + d;
        kh[ko] = __float2bfloat16_rn(kvv);
        sv[tt + i * 8][d] = kv[row * 512 + 256 + h * 32 + d];
    }
    __syncthreads();
#pragma unroll
    for (int i = 0; i < 4; i++) {
        const int dd = tt + i * 8;
        const float v = sv[d][dd];
        const float vhi = bf16rt(v);
        const size_t vo = ((size_t)head * 32 + dd) * T_ + t0 + d;
        vth[vo] = __float2bfloat16_rn(vhi);
        vtl[vo] = __float2bfloat16_rn(v - vhi);
    }
}

// ---------------------------------------------------------------------------
// fp32-input GEMM (prologue only, unchanged)
// ---------------------------------------------------------------------------
#define SPAD 40

__global__ __launch_bounds__(256, 2)
void gemm_f32(const float* __restrict__ A, const float* __restrict__ W,
              float* __restrict__ Cout, int K, int N)
{
    __shared__ __nv_bfloat16 Ahi[128][SPAD];
    __shared__ __nv_bfloat16 Alo[128][SPAD];
    __shared__ __nv_bfloat16 Bhi[64][SPAD];
    __shared__ __nv_bfloat16 Blo[64][SPAD];

    const int tid  = threadIdx.x;
    const int wid  = tid >> 5;
    const int lane = tid & 31;
    const int g    = lane >> 2;
    const int t2   = (lane & 3) << 1;
    const int warp_m = wid & 3;
    const int warp_n = wid >> 2;
    const int rowBase = blockIdx.y * 128;
    const int colBase = blockIdx.x * 64;

    const int a_row = warp_m * 32 + (lane & 15);
    const int a_col = (lane >> 4) * 8;
    const uint32_t aAhi0 = smem_u32(&Ahi[a_row][a_col]);
    const uint32_t aAhi1 = smem_u32(&Ahi[a_row + 16][a_col]);
    const uint32_t aAlo0 = smem_u32(&Alo[a_row][a_col]);
    const uint32_t aAlo1 = smem_u32(&Alo[a_row + 16][a_col]);
    const int b_row = warp_n * 32 + (lane & 7) + ((lane >> 4) << 3);
    const int b_col = ((lane >> 3) & 1) * 8;
    const uint32_t aBhi0 = smem_u32(&Bhi[b_row][b_col]);
    const uint32_t aBhi1 = smem_u32(&Bhi[b_row + 16][b_col]);
    const uint32_t aBlo0 = smem_u32(&Blo[b_row][b_col]);
    const uint32_t aBlo1 = smem_u32(&Blo[b_row + 16][b_col]);

    float acc[2][4][4];
#pragma unroll
    for (int mi = 0; mi < 2; mi++)
#pragma unroll
        for (int ni = 0; ni < 4; ni++)
#pragma unroll
            for (int e = 0; e < 4; e++) acc[mi][ni][e] = 0.f;

    const int nchunks = K >> 5;
    for (int ch = 0; ch < nchunks; ch++) {
        const int k0 = ch << 5;
#pragma unroll
        for (int i = 0; i < 4; i++) {
            const int idx = tid + i * 256;
            const int row = idx >> 3, c4 = idx & 7;
            const float4 v = *(const float4*)(A + (size_t)(rowBase + row) * K + k0 + c4 * 4);
            float hx = bf16rt(v.x), hy = bf16rt(v.y), hz = bf16rt(v.z), hw = bf16rt(v.w);
            *(uint2*)&Ahi[row][c4 * 4] = make_uint2(pack_bf2(hx, hy), pack_bf2(hz, hw));
            *(uint2*)&Alo[row][c4 * 4] = make_uint2(pack_bf2(v.x - hx, v.y - hy),
                                                    pack_bf2(v.z - hz, v.w - hw));
        }
#pragma unroll
        for (int i = 0; i < 2; i++) {
            const int idx = tid + i * 256;
            const int row = idx >> 3, c4 = idx & 7;
            const float4 v = *(const float4*)(W + (size_t)(colBase + row) * K + k0 + c4 * 4);
            float hx = bf16rt(v.x), hy = bf16rt(v.y), hz = bf16rt(v.z), hw = bf16rt(v.w);
            *(uint2*)&Bhi[row][c4 * 4] = make_uint2(pack_bf2(hx, hy), pack_bf2(hz, hw));
            *(uint2*)&Blo[row][c4 * 4] = make_uint2(pack_bf2(v.x - hx, v.y - hy),
                                                    pack_bf2(v.z - hz, v.w - hw));
        }
        __syncthreads();
#pragma unroll
        for (int ks = 0; ks < 2; ks++) {
            const uint32_t ko = ks * 32;
            uint32_t fAhi[2][4], fAlo[2][4], fBhi[4][2], fBlo[4][2];
            LDSM4(fAhi[0][0], fAhi[0][1], fAhi[0][2], fAhi[0][3], aAhi0 + ko);
            LDSM4(fAhi[1][0], fAhi[1][1], fAhi[1][2], fAhi[1][3], aAhi1 + ko);
            LDSM4(fAlo[0][0], fAlo[0][1], fAlo[0][2], fAlo[0][3], aAlo0 + ko);
            LDSM4(fAlo[1][0], fAlo[1][1], fAlo[1][2], fAlo[1][3], aAlo1 + ko);
            LDSM4(fBhi[0][0], fBhi[0][1], fBhi[1][0], fBhi[1][1], aBhi0 + ko);
            LDSM4(fBhi[2][0], fBhi[2][1], fBhi[3][0], fBhi[3][1], aBhi1 + ko);
            LDSM4(fBlo[0][0], fBlo[0][1], fBlo[1][0], fBlo[1][1], aBlo0 + ko);
            LDSM4(fBlo[2][0], fBlo[2][1], fBlo[3][0], fBlo[3][1], aBlo1 + ko);
#pragma unroll
            for (int mi = 0; mi < 2; mi++)
#pragma unroll
                for (int ni = 0; ni < 4; ni++) mma16816(acc[mi][ni], fAhi[mi], fBhi[ni]);
#pragma unroll
            for (int mi = 0; mi < 2; mi++)
#pragma unroll
                for (int ni = 0; ni < 4; ni++) mma16816(acc[mi][ni], fAhi[mi], fBlo[ni]);
#pragma unroll
            for (int mi = 0; mi < 2; mi++)
#pragma unroll
                for (int ni = 0; ni < 4; ni++) mma16816(acc[mi][ni], fAlo[mi], fBhi[ni]);
        }
        __syncthreads();
    }
#pragma unroll
    for (int mi = 0; mi < 2; mi++) {
        const int row0 = rowBase + warp_m * 32 + mi * 16 + g;
#pragma unroll
        for (int ni = 0; ni < 4; ni++) {
            const int col = colBase + warp_n * 32 + ni * 8 + t2;
            *(float2*)(Cout + (size_t)row0 * N + col)       = make_float2(acc[mi][ni][0], acc[mi][ni][1]);
            *(float2*)(Cout + (size_t)(row0 + 8) * N + col) = make_float2(acc[mi][ni][2], acc[mi][ni][3]);
        }
    }
}

// ---------------------------------------------------------------------------
// bf16-input GEMM, double-buffered, one barrier per K-chunk (R13/R15 proven)
// ---------------------------------------------------------------------------
#define STAGE_BYTES 30720
#define A_LO_OFF    10240
#define B_HI_OFF    20480
#define B_LO_OFF    25600
#define GEMM_DYN_SMEM (2 * STAGE_BYTES)

__global__ __launch_bounds__(256, 2)
void gemm_bf(const __nv_bfloat16* __restrict__ Ah, const __nv_bfloat16* __restrict__ Al,
             const __nv_bfloat16* __restrict__ Wh, const __nv_bfloat16* __restrict__ Wl,
             const float* __restrict__ bias, float* __restrict__ Cout, int K, int N)
{
    extern __shared__ __align__(128) uint8_t dynsm[];
    __shared__ float s_bias[64];

    const uint32_t sbase = smem_u32(dynsm);
    const int tid  = threadIdx.x;
    const int wid  = tid >> 5;
    const int lane = tid & 31;
    const int g    = lane >> 2;
    const int t2   = (lane & 3) << 1;
    const int warp_m = wid & 3;
    const int warp_n = wid >> 2;
    const int rowBase = blockIdx.y * 128;
    const int colBase = blockIdx.x * 64;

    if (tid < 64) s_bias[tid] = bias ? bias[colBase + tid] : 0.f;

    const int a_row = warp_m * 32 + (lane & 15);
    const int a_col = (lane >> 4) * 8;
    const uint32_t oAhi0 = (uint32_t)(a_row * SPAD + a_col) * 2;
    const uint32_t oAhi1 = oAhi0 + 16 * SPAD * 2;
    const uint32_t oAlo0 = oAhi0 + A_LO_OFF;
    const uint32_t oAlo1 = oAhi1 + A_LO_OFF;
    const int b_row = warp_n * 32 + (lane & 7) + ((lane >> 4) << 3);
    const int b_col = ((lane >> 3) & 1) * 8;
    const uint32_t oBhi0 = B_HI_OFF + (uint32_t)(b_row * SPAD + b_col) * 2;
    const uint32_t oBhi1 = oBhi0 + 16 * SPAD * 2;
    const uint32_t oBlo0 = oBhi0 + (B_LO_OFF - B_HI_OFF);
    const uint32_t oBlo1 = oBhi1 + (B_LO_OFF - B_HI_OFF);

    const int ar0 = tid >> 2, as0 = (tid & 3) * 8;
    const uint32_t sA0 = (uint32_t)(ar0 * SPAD + as0) * 2;
    const uint32_t sA1 = (uint32_t)((ar0 + 64) * SPAD + as0) * 2;
    const uint32_t sB  = B_HI_OFF + (uint32_t)(ar0 * SPAD + as0) * 2;

    float acc[2][4][4];
#pragma unroll
    for (int mi = 0; mi < 2; mi++)
#pragma unroll
        for (int ni = 0; ni < 4; ni++)
#pragma unroll
            for (int e = 0; e < 4; e++) acc[mi][ni][e] = 0.f;

    const int nchunks = K >> 5;
    uint4 pah[2], pal[2], pbh, pbl;

    auto prefetch = [&](int ch) {
        const int k0 = ch << 5;
#pragma unroll
        for (int i = 0; i < 2; i++) {
            const int row = ar0 + i * 64;
            pah[i] = *(const uint4*)(Ah + (size_t)(rowBase + row) * K + k0 + as0);
            pal[i] = *(const uint4*)(Al + (size_t)(rowBase + row) * K + k0 + as0);
        }
        pbh = *(const uint4*)(Wh + (size_t)(colBase + ar0) * K + k0 + as0);
        pbl = *(const uint4*)(Wl + (size_t)(colBase + ar0) * K + k0 + as0);
    };

    prefetch(0);

    for (int ch = 0; ch < nchunks; ch++) {
        const uint32_t soff = (uint32_t)(ch & 1) * STAGE_BYTES;
        uint8_t* stg = dynsm + soff;
        *(uint4*)(stg + sA0)            = pah[0];
        *(uint4*)(stg + sA1)            = pah[1];
        *(uint4*)(stg + sA0 + A_LO_OFF) = pal[0];
        *(uint4*)(stg + sA1 + A_LO_OFF) = pal[1];
        *(uint4*)(stg + sB)             = pbh;
        *(uint4*)(stg + sB + (B_LO_OFF - B_HI_OFF)) = pbl;
        __syncthreads();

        if (ch + 1 < nchunks) prefetch(ch + 1);

        const uint32_t sb = sbase + soff;
#pragma unroll
        for (int ks = 0; ks < 2; ks++) {
            const uint32_t ko = ks * 32;
            uint32_t fAhi[2][4], fAlo[2][4], fBhi[4][2], fBlo[4][2];
            LDSM4(fAhi[0][0], fAhi[0][1], fAhi[0][2], fAhi[0][3], sb + oAhi0 + ko);
            LDSM4(fAhi[1][0], fAhi[1][1], fAhi[1][2], fAhi[1][3], sb + oAhi1 + ko);
            LDSM4(fAlo[0][0], fAlo[0][1], fAlo[0][2], fAlo[0][3], sb + oAlo0 + ko);
            LDSM4(fAlo[1][0], fAlo[1][1], fAlo[1][2], fAlo[1][3], sb + oAlo1 + ko);
            LDSM4(fBhi[0][0], fBhi[0][1], fBhi[1][0], fBhi[1][1], sb + oBhi0 + ko);
            LDSM4(fBhi[2][0], fBhi[2][1], fBhi[3][0], fBhi[3][1], sb + oBhi1 + ko);
            LDSM4(fBlo[0][0], fBlo[0][1], fBlo[1][0], fBlo[1][1], sb + oBlo0 + ko);
            LDSM4(fBlo[2][0], fBlo[2][1], fBlo[3][0], fBlo[3][1], sb + oBlo1 + ko);
#pragma unroll
            for (int mi = 0; mi < 2; mi++)
#pragma unroll
                for (int ni = 0; ni < 4; ni++) mma16816(acc[mi][ni], fAhi[mi], fBhi[ni]);
#pragma unroll
            for (int mi = 0; mi < 2; mi++)
#pragma unroll
                for (int ni = 0; ni < 4; ni++) mma16816(acc[mi][ni], fAhi[mi], fBlo[ni]);
#pragma unroll
            for (int mi = 0; mi < 2; mi++)
#pragma unroll
                for (int ni = 0; ni < 4; ni++) mma16816(acc[mi][ni], fAlo[mi], fBhi[ni]);
        }
    }

#pragma unroll
    for (int mi = 0; mi < 2; mi++) {
        const int row0 = rowBase + warp_m * 32 + mi * 16 + g;
#pragma unroll
        for (int ni = 0; ni < 4; ni++) {
            const int cl = warp_n * 32 + ni * 8 + t2;
            const int col = colBase + cl;
            const float bx = s_bias[cl], by = s_bias[cl + 1];
            *(float2*)(Cout + (size_t)row0 * N + col) =
                make_float2(acc[mi][ni][0] + bx, acc[mi][ni][1] + by);
            *(float2*)(Cout + (size_t)(row0 + 8) * N + col) =
                make_float2(acc[mi][ni][2] + bx, acc[mi][ni][3] + by);
        }
    }
}

// ---------------------------------------------------------------------------
// Tensor-core flash attention (unchanged from R15)
// ---------------------------------------------------------------------------
#define ACHUNK 128
#define VSPAD  136
#define AST_VHI 10240
#define AST_VLO 18944
#define AST_BYTES 27648
#define ATTN_DYN_SMEM (2 * AST_BYTES)

__global__ __launch_bounds__(256)
void attn_mma(const float* __restrict__ q,
              const __nv_bfloat16* __restrict__ khg,
              const __nv_bfloat16* __restrict__ vthg, const __nv_bfloat16* __restrict__ vtlg,
              __nv_bfloat16* __restrict__ ath, __nv_bfloat16* __restrict__ atl)
{
    extern __shared__ __align__(128) uint8_t dynsm[];

    const int bx    = blockIdx.x;
    const int head  = bx >> 1;
    const int qhalf = bx & 1;
    const int b   = head / (J_ * H_);
    const int rem = head % (J_ * H_);
    const int j   = rem / H_;
    const int h   = rem % H_;
    const int tid  = threadIdx.x;
    const int wid  = tid >> 5;
    const int lane = tid & 31;
    const int g    = lane >> 2;
    const int t2   = (lane & 3) << 1;

    const uint32_t sbase = smem_u32(dynsm);

    const __nv_bfloat16* khb = khg + (size_t)head * T_ * D_;
    const __nv_bfloat16* vhb = vthg + (size_t)head * D_ * T_;
    const __nv_bfloat16* vlb = vtlg + (size_t)head * D_ * T_;

    const size_t qStride = (size_t)J_ * C_;
    const float* qb = q + (size_t)b * T_ * J_ * C_ + (size_t)j * C_ + h * D_;
    const size_t atoff = (size_t)b * T_ * J_ * C_ + (size_t)j * C_ + h * D_;

    const int qbase = qhalf * 256 + wid * 32;

    const int k_row = (lane & 7) + ((lane >> 4) << 3);
    const int k_col = ((lane >> 3) & 1) * 8;
    const uint32_t oKhi = (uint32_t)(k_row * SPAD + k_col) * 2;
    const uint32_t oVhi0 = AST_VHI + (uint32_t)(k_row * VSPAD + k_col) * 2;
    const uint32_t oVhi1 = oVhi0 + 16 * VSPAD * 2;
    const uint32_t oVlo0 = oVhi0 + (AST_VLO - AST_VHI);
    const uint32_t oVlo1 = oVhi1 + (AST_VLO - AST_VHI);

    const float qscale = 0.17677669529663687f * 1.4426950408889634f;
    uint32_t Qhi[2][2][4];
#pragma unroll
    for (int mt = 0; mt < 2; mt++)
#pragma unroll
        for (int kt = 0; kt < 2; kt++)
#pragma unroll
            for (int e = 0; e < 4; e++) {
                const int row = qbase + mt * 16 + g + ((e & 1) ? 8 : 0);
                const int col = kt * 16 + t2 + ((e & 2) ? 8 : 0);
                float2 v = *(const float2*)(qb + (size_t)row * qStride + col);
                Qhi[mt][kt][e] = pack_bf2(v.x * qscale, v.y * qscale);
            }

    float O[2][4][4];
#pragma unroll
    for (int mt = 0; mt < 2; mt++)
#pragma unroll
        for (int d = 0; d < 4; d++)
#pragma unroll
            for (int e = 0; e < 4; e++) O[mt][d][e] = 0.f;
    float l[2][2] = {{0.f, 0.f}, {0.f, 0.f}};

    const int nchunks = T_ / ACHUNK;   // 4
    for (int cc = 0; cc < nchunks; cc++) {
        const int c0 = cc * ACHUNK;
        const uint32_t soff = (uint32_t)(cc & 1) * AST_BYTES;
        uint8_t* stg = dynsm + soff;

        for (int i = tid; i < 512; i += 256) {
            const int r = i >> 2, seg = (i & 3) * 8;
            *(uint4*)(stg + (uint32_t)(r * SPAD + seg) * 2) =
                *(const uint4*)(khb + (size_t)(c0 + r) * D_ + seg);
        }
        for (int i = tid; i < 512; i += 256) {
            const int d = i >> 4, seg = (i & 15) * 8;
            *(uint4*)(stg + AST_VHI + (uint32_t)(d * VSPAD + seg) * 2) =
                *(const uint4*)(vhb + (size_t)d * T_ + c0 + seg);
            *(uint4*)(stg + AST_VLO + (uint32_t)(d * VSPAD + seg) * 2) =
                *(const uint4*)(vlb + (size_t)d * T_ + c0 + seg);
        }
        __syncthreads();

        const uint32_t sb = sbase + soff;
#pragma unroll 1
        for (int s = 0; s < ACHUNK / 16; s++) {
            const int key0 = s * 16;
            const uint32_t krow_off = (uint32_t)key0 * (SPAD * 2);
            const uint32_t vcol_off = (uint32_t)key0 * 2;

            uint32_t kh[2][2][2];
            LDSM4(kh[0][0][0], kh[0][0][1], kh[1][0][0], kh[1][0][1], sb + oKhi + krow_off);
            LDSM4(kh[0][1][0], kh[0][1][1], kh[1][1][0], kh[1][1][1], sb + oKhi + krow_off + 32);

            float S[2][2][4];
#pragma unroll
            for (int mt = 0; mt < 2; mt++)
#pragma unroll
                for (int nt = 0; nt < 2; nt++)
#pragma unroll
                    for (int e = 0; e < 4; e++) S[mt][nt][e] = 0.f;
#pragma unroll
            for (int mt = 0; mt < 2; mt++)
#pragma unroll
                for (int nt = 0; nt < 2; nt++) mma16816(S[mt][nt], Qhi[mt][0], kh[nt][0]);
#pragma unroll
            for (int mt = 0; mt < 2; mt++)
#pragma unroll
                for (int nt = 0; nt < 2; nt++) mma16816(S[mt][nt], Qhi[mt][1], kh[nt][1]);

            uint32_t vh[4][2], vl[4][2];
            LDSM4(vh[0][0], vh[0][1], vh[1][0], vh[1][1], sb + oVhi0 + vcol_off);
            LDSM4(vh[2][0], vh[2][1], vh[3][0], vh[3][1], sb + oVhi1 + vcol_off);
            LDSM4(vl[0][0], vl[0][1], vl[1][0], vl[1][1], sb + oVlo0 + vcol_off);
            LDSM4(vl[2][0], vl[2][1], vl[3][0], vl[3][1], sb + oVlo1 + vcol_off);

            uint32_t Ph[2][4], Pl[2][4];
#pragma unroll
            for (int mt = 0; mt < 2; mt++) {
                const float p00 = exp2n(S[mt][0][0]);
                const float p01 = exp2n(S[mt][0][1]);
                const float p02 = exp2n(S[mt][0][2]);
                const float p03 = exp2n(S[mt][0][3]);
                const float p10 = exp2n(S[mt][1][0]);
                const float p11 = exp2n(S[mt][1][1]);
                const float p12 = exp2n(S[mt][1][2]);
                const float p13 = exp2n(S[mt][1][3]);
                l[mt][0] += p00 + p01 + p10 + p11;
                l[mt][1] += p02 + p03 + p12 + p13;
                float h00 = bf16rt(p00), h01 = bf16rt(p01), h02 = bf16rt(p02), h03 = bf16rt(p03);
                float h10 = bf16rt(p10), h11 = bf16rt(p11), h12 = bf16rt(p12), h13 = bf16rt(p13);
                Ph[mt][0] = pack_bf2(h00, h01); Pl[mt][0] = pack_bf2(p00 - h00, p01 - h01);
                Ph[mt][1] = pack_bf2(h02, h03); Pl[mt][1] = pack_bf2(p02 - h02, p03 - h03);
                Ph[mt][2] = pack_bf2(h10, h11); Pl[mt][2] = pack_bf2(p10 - h10, p11 - h11);
                Ph[mt][3] = pack_bf2(h12, h13); Pl[mt][3] = pack_bf2(p12 - h12, p13 - h13);
            }

#pragma unroll
            for (int mt = 0; mt < 2; mt++)
#pragma unroll
                for (int dn = 0; dn < 4; dn++) mma16816(O[mt][dn], Ph[mt], vh[dn]);
#pragma unroll
            for (int mt = 0; mt < 2; mt++)
#pragma unroll
                for (int dn = 0; dn < 4; dn++) mma16816(O[mt][dn], Ph[mt], vl[dn]);
#pragma unroll
            for (int mt = 0; mt < 2; mt++)
#pragma unroll
                for (int dn = 0; dn < 4; dn++) mma16816(O[mt][dn], Pl[mt], vh[dn]);
        }
    }

#pragma unroll
    for (int mt = 0; mt < 2; mt++) {
        float l0 = l[mt][0], l1 = l[mt][1];
        l0 += __shfl_xor_sync(0xffffffffu, l0, 1);
        l0 += __shfl_xor_sync(0xffffffffu, l0, 2);
        l1 += __shfl_xor_sync(0xffffffffu, l1, 1);
        l1 += __shfl_xor_sync(0xffffffffu, l1, 2);
        const float inv0 = 1.f / l0;
        const float inv1 = 1.f / l1;
        const int r0 = qbase + mt * 16 + g;
        const int r1 = r0 + 8;
#pragma unroll
        for (int dn = 0; dn < 4; dn++) {
            const int col = dn * 8 + t2;
            const float a0 = O[mt][dn][0] * inv0, a1 = O[mt][dn][1] * inv0;
            const float a2 = O[mt][dn][2] * inv1, a3 = O[mt][dn][3] * inv1;
            const float h0 = bf16rt(a0), h1 = bf16rt(a1), h2 = bf16rt(a2), h3 = bf16rt(a3);
            *(uint32_t*)(ath + atoff + (size_t)r0 * qStride + col) = pack_bf2(h0, h1);
            *(uint32_t*)(atl + atoff + (size_t)r0 * qStride + col) = pack_bf2(a0 - h0, a1 - h1);
            *(uint32_t*)(ath + atoff + (size_t)r1 * qStride + col) = pack_bf2(h2, h3);
            *(uint32_t*)(atl + atoff + (size_t)r1 * qStride + col) = pack_bf2(a2 - h2, a3 - h3);
        }
    }
}

// ---------------------------------------------------------------------------
extern "C" void kernel_launch(void* const* d_in, const int* in_sizes, int n_in,
                              void* d_out, int out_size)
{
    (void)in_sizes; (void)n_in; (void)out_size;
    const float* x   = (const float*)d_in[0];
    const float* Wq  = (const float*)d_in[1];
    const float* Wkv = (const float*)d_in[2];
    const float* Wc1 = (const float*)d_in[3];
    const float* bc1 = (const float*)d_in[4];
    const float* Wc2 = (const float*)d_in[5];
    const float* bc2 = (const float*)d_in[6];
    const float* Wp  = (const float*)d_in[7];
    const float* bp  = (const float*)d_in[8];
    float* out = (float*)d_out;

    float *y, *kv, *q, *wc2t, *wf, *bq;
    cudaGetSymbolAddress((void**)&y,    g_y);
    cudaGetSymbolAddress((void**)&kv,   g_kv);
    cudaGetSymbolAddress((void**)&q,    g_q);
    cudaGetSymbolAddress((void**)&wc2t, g_wc2t);
    cudaGetSymbolAddress((void**)&wf,   g_wf);
    cudaGetSymbolAddress((void**)&bq,   g_bq);

    __nv_bfloat16 *xh, *xl, *gh, *gl, *ath, *atl, *kh, *vth, *vtl;
    __nv_bfloat16 *wc1h, *wc1l, *wkvh, *wkvl, *wfh, *wfl, *wph, *wpl;
    cudaGetSymbolAddress((void**)&xh,  g_xh);   cudaGetSymbolAddress((void**)&xl,  g_xl);
    cudaGetSymbolAddress((void**)&gh,  g_gh);   cudaGetSymbolAddress((void**)&gl,  g_gl);
    cudaGetSymbolAddress((void**)&ath, g_ath);  cudaGetSymbolAddress((void**)&atl, g_atl);
    cudaGetSymbolAddress((void**)&kh,  g_kh);
    cudaGetSymbolAddress((void**)&vth, g_vth);  cudaGetSymbolAddress((void**)&vtl, g_vtl);
    cudaGetSymbolAddress((void**)&wc1h, g_wc1h); cudaGetSymbolAddress((void**)&wc1l, g_wc1l);
    cudaGetSymbolAddress((void**)&wkvh, g_wkvh); cudaGetSymbolAddress((void**)&wkvl, g_wkvl);
    cudaGetSymbolAddress((void**)&wfh,  g_wfh);  cudaGetSymbolAddress((void**)&wfl,  g_wfl);
    cudaGetSymbolAddress((void**)&wph,  g_wph);  cudaGetSymbolAddress((void**)&wpl,  g_wpl);

    cudaFuncSetAttribute(gemm_bf,  cudaFuncAttributeMaxDynamicSharedMemorySize, GEMM_DYN_SMEM);
    cudaFuncSetAttribute(attn_mma, cudaFuncAttributeMaxDynamicSharedMemorySize, ATTN_DYN_SMEM);

    const dim3 blk(256);
    const int mt = NROWS / 128;  // 272 row tiles

    // --- prologue: weight folding + merged splits ---
    transpose_wc2<<<dim3(16, 8), dim3(32, 8)>>>(Wc2, wc2t);
    gemm_f32<<<dim3(8, 2), blk>>>(Wq, wc2t, wf, 256, 512);
    fold_bias<<<32, 256>>>(Wq, bc2, bq);
    split_all<<<9152, 256>>>(Wc1, Wkv, wf, Wp, x,
                             (uint2*)wc1h, (uint2*)wc1l, (uint2*)wkvh, (uint2*)wkvl,
                             (uint2*)wfh, (uint2*)wfl, (uint2*)wph, (uint2*)wpl,
                             (uint2*)xh, (uint2*)xl);

    // --- main pipeline (R15-proven separate launches) ---
    gemm_bf<<<dim3(8, mt), blk, GEMM_DYN_SMEM>>>(xh, xl, wc1h, wc1l, bc1, y,  256, 512);
    gemm_bf<<<dim3(8, mt), blk, GEMM_DYN_SMEM>>>(xh, xl, wkvh, wkvl, nullptr, kv, 256, 512);
    conv_g<<<NROWS * 128 / 256, 256>>>(y, (uint2*)gh, (uint2*)gl);
    gemm_bf<<<dim3(4, mt), blk, GEMM_DYN_SMEM>>>(gh, gl, wfh, wfl, bq, q, 512, 256);
    conv_kv<<<dim3(16, NHEAD), 256>>>(kv, kh, vth, vtl);
    attn_mma<<<NHEAD * 2, 256, ATTN_DYN_SMEM>>>(q, kh, vth, vtl, ath, atl);
    gemm_bf<<<dim3(4, mt), blk, GEMM_DYN_SMEM>>>(ath, atl, wph, wpl, bp, out, 256, 256);
}